// round 7
// baseline (speedup 1.0000x reference)
#include <cuda_runtime.h>
#include <cstdint>
#include <cstddef>

// out[b,s,d] = 16*sum_v x[b,s,v]*emb[v,d] + pos[s,d]*any(x[b,s,:])
// x in {0,1} -> exact int8 GEMM. emb*16 quantized per-column d:
//   emb16[v,d] = s_d*(hi[v,d] + lo[v,d]/128),  hi,lo int8, s_d = 16*max_v|emb|/127
// Two s32 accumulators (hi,lo) share the A (x) operand; epilogue recombines in fp32.
// mma.sync.m16n8k32.s8 (baseline PTX; tcgen05 unavailable: harness targets compute_103).

static constexpr int DIM_S = 1024;
static constexpr int DIM_V = 8192;
static constexpr int DIM_D = 256;

static constexpr int TM   = 64;            // CTA M tile
static constexpr int TKB  = 64;            // real K per stage (int8 bytes)
static constexpr int NST  = DIM_V / TKB;   // 128 stages
static constexpr int RING = 4;

static constexpr uint32_t A_BYTES  = TM * TKB;        // 4 KB
static constexpr uint32_t B_BYTES  = DIM_D * TKB;     // 16 KB per table
static constexpr uint32_t OFF_BH   = A_BYTES;
static constexpr uint32_t OFF_BL   = A_BYTES + B_BYTES;
static constexpr uint32_t ST_BYTES = A_BYTES + 2 * B_BYTES;   // 36 KB
static constexpr uint32_t SMEM_DYN = RING * ST_BYTES + 1024;  // ~145 KB

// Quantized transposed tables: [d][v] int8 (2 MB each), per-column scale.
__device__ __align__(16) signed char g_qhi[(size_t)DIM_D * DIM_V];
__device__ __align__(16) signed char g_qlo[(size_t)DIM_D * DIM_V];
__device__ float g_scale[DIM_D];
__device__ int   g_colmax[DIM_D];

__device__ __forceinline__ uint32_t smem_u32(const void* p) {
    return (uint32_t)__cvta_generic_to_shared(p);
}
// bank-stagger swizzle for 64B rows: granule g = (row*4 + ((k>>4)^((row>>1)&3)))%8
__device__ __forceinline__ uint32_t swz_row(uint32_t row) {
    return ((row >> 1) & 3u) << 4;
}

// ---------------------------------------------------------------------------
// Prep kernels
// ---------------------------------------------------------------------------
__global__ void zero_colmax() { g_colmax[threadIdx.x] = 0; }

__global__ void colmax_kernel(const float* __restrict__ emb) {
    const int t = threadIdx.x;               // = d
    const int v0 = blockIdx.x * 32;
    float m = 0.0f;
#pragma unroll 8
    for (int r = 0; r < 32; ++r)
        m = fmaxf(m, fabsf(emb[(size_t)(v0 + r) * DIM_D + t]));
    atomicMax(&g_colmax[t], __float_as_int(m));  // all >=0: int order == float order
}

__global__ void quant_kernel(const float* __restrict__ emb) {
    __shared__ float tile[32][33];
    const int v0 = blockIdx.x * 32, d0 = blockIdx.y * 32, t = threadIdx.x;
#pragma unroll
    for (int it = 0; it < 4; ++it) {
        int idx = t + it * 256, i = idx >> 5, j = idx & 31;
        tile[i][j] = emb[(size_t)(v0 + i) * DIM_D + d0 + j];
    }
    __syncthreads();
    const int dl = t >> 3, vq = t & 7;
    const float m = __int_as_float(g_colmax[d0 + dl]) * 16.0f;
    float s, inv, invlo;
    if (m < 1e-20f) { s = 1.0f; inv = 0.0f; invlo = 0.0f; }
    else { s = m * (1.0f / 127.0f); inv = 127.0f / m; invlo = 128.0f / s; }
    uint32_t ph = 0, pl = 0;
#pragma unroll
    for (int u = 0; u < 4; ++u) {
        float e = tile[vq * 4 + u][dl] * 16.0f;
        float h = fminf(fmaxf(rintf(e * inv), -127.0f), 127.0f);
        float r = fmaf(-h, s, e);
        float l = fminf(fmaxf(rintf(r * invlo), -127.0f), 127.0f);
        ph |= ((uint32_t)(int)h & 0xFFu) << (8 * u);
        pl |= ((uint32_t)(int)l & 0xFFu) << (8 * u);
    }
    size_t off = (size_t)(d0 + dl) * DIM_V + v0 + vq * 4;
    *reinterpret_cast<uint32_t*>(&g_qhi[off]) = ph;
    *reinterpret_cast<uint32_t*>(&g_qlo[off]) = pl;
    if (blockIdx.x == 0 && vq == 0) g_scale[d0 + dl] = s;
}

// ---------------------------------------------------------------------------
// Producer helpers (512 threads)
// ---------------------------------------------------------------------------
__device__ __forceinline__ void load_a(int4* va, const int* __restrict__ x,
                                       int m0, int stage, int t) {
    const int4* xr = reinterpret_cast<const int4*>(x);
#pragma unroll
    for (int i = 0; i < 2; ++i) {
        int idx = t + i * 512;
        int row = idx >> 4, q = idx & 15;        // 64 rows x 16 int4 (64 v)
        va[i] = xr[(size_t)(m0 + row) * (DIM_V / 4) + (size_t)stage * 16 + q];
    }
}

__device__ __forceinline__ void store_a(const int4* va, uint32_t abase,
                                        int t, int* flags) {
#pragma unroll
    for (int i = 0; i < 2; ++i) {
        int idx = t + i * 512;
        int row = idx >> 4, q = idx & 15;
        int4 v = va[i];
        if (v.x | v.y | v.z | v.w) flags[row] = 1;
        uint32_t pk = (uint32_t)v.x | ((uint32_t)v.y << 8) |
                      ((uint32_t)v.z << 16) | ((uint32_t)v.w << 24);
        uint32_t dst = abase + (uint32_t)row * 64u +
                       (((uint32_t)q * 4u) ^ swz_row((uint32_t)row));
        asm volatile("st.shared.b32 [%0], %1;" :: "r"(dst), "r"(pk));
    }
}

__device__ __forceinline__ void issue_b(uint32_t sbase, int stage, int t) {
#pragma unroll
    for (int i = 0; i < 2; ++i) {
        int idx = t + i * 512;
        int row = idx >> 2, seg = idx & 3;       // 256 rows x 4 x 16B
        uint32_t koff = ((uint32_t)seg * 16u) ^ swz_row((uint32_t)row);
        uint32_t dsth = sbase + OFF_BH + (uint32_t)row * 64u + koff;
        uint32_t dstl = sbase + OFF_BL + (uint32_t)row * 64u + koff;
        const void* srch = &g_qhi[(size_t)row * DIM_V + (size_t)stage * 64 + seg * 16];
        const void* srcl = &g_qlo[(size_t)row * DIM_V + (size_t)stage * 64 + seg * 16];
        asm volatile("cp.async.cg.shared.global [%0], [%1], 16;" :: "r"(dsth), "l"(srch));
        asm volatile("cp.async.cg.shared.global [%0], [%1], 16;" :: "r"(dstl), "l"(srcl));
    }
}

#define IMMA(c, a, b0, b1)                                                     \
    asm volatile("mma.sync.aligned.m16n8k32.row.col.s32.s8.s8.s32 "            \
                 "{%0,%1,%2,%3}, {%4,%5,%6,%7}, {%8,%9}, {%0,%1,%2,%3};"       \
                 : "+r"((c)[0]), "+r"((c)[1]), "+r"((c)[2]), "+r"((c)[3])      \
                 : "r"((a)[0]), "r"((a)[1]), "r"((a)[2]), "r"((a)[3]),         \
                   "r"(b0), "r"(b1))

// ---------------------------------------------------------------------------
// GEMM: 128 CTAs x 512 thr; CTA 64x256; 16 warps (2M x 8N); warp 32x32.
// ---------------------------------------------------------------------------
__global__ __launch_bounds__(512, 1)
void multihot_gemm(const int* __restrict__ x, const float* __restrict__ pos,
                   float* __restrict__ out) {
    extern __shared__ char dynsm[];
    __shared__ int flags[TM];

    const int t = threadIdx.x;
    const int wid = t >> 5, lane = t & 31;
    const int wm = wid & 1, wn = wid >> 1;      // wm 0..1, wn 0..7
    const int m0 = blockIdx.x * TM;

    const uint32_t base = (smem_u32(dynsm) + 1023u) & ~1023u;

    for (int i = t; i < TM; i += 512) flags[i] = 0;
    __syncthreads();

    int hacc[2][4][4], lacc[2][4][4];
#pragma unroll
    for (int a = 0; a < 2; ++a)
#pragma unroll
        for (int b = 0; b < 4; ++b)
#pragma unroll
            for (int c = 0; c < 4; ++c) { hacc[a][b][c] = 0; lacc[a][b][c] = 0; }

    // prologue
    int4 va[2];
    load_a(va, x, m0, 0, t);
#pragma unroll
    for (int s = 0; s < RING - 1; ++s) {
        uint32_t sb = base + (uint32_t)s * ST_BYTES;
        store_a(va, sb, t, flags);
        issue_b(sb, s, t);
        asm volatile("cp.async.commit_group;" ::: "memory");
        load_a(va, x, m0, s + 1, t);
    }

    // per-lane address precompute
    const uint32_t swz_a = (((uint32_t)(lane & 15) >> 1) & 3u) << 4;
    const uint32_t a_koff = ((uint32_t)(lane >> 4)) * 16u;
    uint32_t a_row[2];
#pragma unroll
    for (int mt = 0; mt < 2; ++mt)
        a_row[mt] = (uint32_t)(wm * 32 + mt * 16 + (lane & 15)) * 64u;

    uint32_t b_off[4], b_swz[4];
    const uint32_t b_k = (uint32_t)(lane & 3) * 4u;
#pragma unroll
    for (int nt = 0; nt < 4; ++nt) {
        uint32_t n = (uint32_t)(wn * 32 + nt * 8 + (lane >> 2));
        b_off[nt] = n * 64u;
        b_swz[nt] = swz_row(n);
    }

    // mainloop
#pragma unroll 1
    for (int k = 0; k < NST; ++k) {
        asm volatile("cp.async.wait_group %0;" :: "n"(RING - 2) : "memory");
        __syncthreads();

        if (k + RING - 1 < NST) {
            uint32_t sb = base + (uint32_t)((k + RING - 1) & (RING - 1)) * ST_BYTES;
            store_a(va, sb, t, flags);
            issue_b(sb, k + RING - 1, t);
        }
        if (k + RING < NST) load_a(va, x, m0, k + RING, t);
        asm volatile("cp.async.commit_group;" ::: "memory");

        const uint32_t sb = base + (uint32_t)(k & (RING - 1)) * ST_BYTES;
#pragma unroll
        for (int ks = 0; ks < 2; ++ks) {
            const uint32_t kb = (uint32_t)ks * 32u;
            uint32_t af[2][4];
#pragma unroll
            for (int mt = 0; mt < 2; ++mt) {
                uint32_t addr = sb + a_row[mt] + ((kb + a_koff) ^ swz_a);
                asm volatile("ldmatrix.sync.aligned.m8n8.x4.shared.b16 "
                             "{%0,%1,%2,%3}, [%4];"
                             : "=r"(af[mt][0]), "=r"(af[mt][1]),
                               "=r"(af[mt][2]), "=r"(af[mt][3])
                             : "r"(addr));
            }
            uint32_t bf[4][2];
            // hi table
#pragma unroll
            for (int nt = 0; nt < 4; ++nt) {
                uint32_t a0 = sb + OFF_BH + b_off[nt] + ((kb + b_k) ^ b_swz[nt]);
                asm volatile("ld.shared.b32 %0, [%1];" : "=r"(bf[nt][0]) : "r"(a0));
                asm volatile("ld.shared.b32 %0, [%1];" : "=r"(bf[nt][1]) : "r"(a0 ^ 16u));
            }
#pragma unroll
            for (int mt = 0; mt < 2; ++mt)
#pragma unroll
                for (int nt = 0; nt < 4; ++nt)
                    IMMA(hacc[mt][nt], af[mt], bf[nt][0], bf[nt][1]);
            // lo table
#pragma unroll
            for (int nt = 0; nt < 4; ++nt) {
                uint32_t a0 = sb + OFF_BL + b_off[nt] + ((kb + b_k) ^ b_swz[nt]);
                asm volatile("ld.shared.b32 %0, [%1];" : "=r"(bf[nt][0]) : "r"(a0));
                asm volatile("ld.shared.b32 %0, [%1];" : "=r"(bf[nt][1]) : "r"(a0 ^ 16u));
            }
#pragma unroll
            for (int mt = 0; mt < 2; ++mt)
#pragma unroll
                for (int nt = 0; nt < 4; ++nt)
                    IMMA(lacc[mt][nt], af[mt], bf[nt][0], bf[nt][1]);
        }
    }

    __syncthreads();   // flags fully written

    // epilogue: out = s_d*(hi + lo/128) + pos*any_tok
#pragma unroll
    for (int mt = 0; mt < 2; ++mt) {
#pragma unroll
        for (int half = 0; half < 2; ++half) {
            const int rl = wm * 32 + mt * 16 + (lane >> 2) + half * 8;
            const int grow = m0 + rl;
            const float tokf = flags[rl] ? 1.0f : 0.0f;
            const float* prow = pos + (size_t)(grow & (DIM_S - 1)) * DIM_D;
            float* orow = out + (size_t)grow * DIM_D;
#pragma unroll
            for (int nt = 0; nt < 4; ++nt) {
                const int col = wn * 32 + nt * 8 + (lane & 3) * 2;
                float2 sc = *reinterpret_cast<const float2*>(&g_scale[col]);
                float2 pv = *reinterpret_cast<const float2*>(prow + col);
                float h0 = (float)hacc[mt][nt][half * 2 + 0];
                float h1 = (float)hacc[mt][nt][half * 2 + 1];
                float l0 = (float)lacc[mt][nt][half * 2 + 0];
                float l1 = (float)lacc[mt][nt][half * 2 + 1];
                float2 o;
                o.x = sc.x * fmaf(l0, 0.0078125f, h0) + pv.x * tokf;
                o.y = sc.y * fmaf(l1, 0.0078125f, h1) + pv.y * tokf;
                *reinterpret_cast<float2*>(orow + col) = o;
            }
        }
    }
}

// ---------------------------------------------------------------------------
extern "C" void kernel_launch(void* const* d_in, const int* in_sizes, int n_in,
                              void* d_out, int out_size) {
    (void)in_sizes; (void)n_in; (void)out_size;
    const int*   x   = (const int*)d_in[0];     // [8,1024,8192] int32 (0/1)
    const float* emb = (const float*)d_in[1];   // [8192,256] f32
    const float* pos = (const float*)d_in[2];   // [1,1024,256] f32
    float* out = (float*)d_out;                 // [8,1024,256] f32

    cudaFuncSetAttribute(multihot_gemm,
                         cudaFuncAttributeMaxDynamicSharedMemorySize, SMEM_DYN);

    zero_colmax<<<1, DIM_D>>>();
    colmax_kernel<<<DIM_V / 32, DIM_D>>>(emb);
    quant_kernel<<<dim3(DIM_V / 32, DIM_D / 32), 256>>>(emb);
    multihot_gemm<<<(8 * DIM_S) / TM, 512, SMEM_DYN>>>(x, pos, out);
}

// round 8
// speedup vs baseline: 4.1650x; 4.1650x over previous
#include <cuda_runtime.h>
#include <cuda_fp16.h>
#include <cstdint>
#include <cstddef>

// out[b,s,d] = 16*sum_v x[b,s,v]*emb[v,d] + pos[s,d]*any(x[b,s,:])
// GEMM M=8192, N=256, K=8192. Single-pass fp16: table = fp16(emb*16),
// x in {0,1} exact in fp16, fp32 accumulate. Output rel-RMS ~2.8e-4 < 1e-3.
// Baseline PTX path (harness targets compute_103: no tcgen05). R7 showed
// int8 mma.sync is ~8x slower per instr than fp16 HMMA on sm_103 -> fp16.

static constexpr int DIM_S = 1024;
static constexpr int DIM_V = 8192;
static constexpr int DIM_D = 256;

static constexpr int TM     = 64;           // CTA M tile
static constexpr int TKB    = 64;           // K per stage
static constexpr int NSTAGE = DIM_V / TKB;  // 128
static constexpr int RING   = 4;

static constexpr uint32_t A_BYTES  = TM * TKB * 2;        // 8 KB
static constexpr uint32_t B_BYTES  = DIM_D * TKB * 2;     // 32 KB
static constexpr uint32_t ST_BYTES = A_BYTES + B_BYTES;   // 40 KB
static constexpr uint32_t SMEM_DYN = RING * ST_BYTES + 1024;

// Transposed fp16 table: [d][v], value = fp16(emb[v][d] * 16). 4 MB.
__device__ __align__(128) unsigned short g_embT[(size_t)DIM_D * DIM_V];

__device__ __forceinline__ uint32_t smem_u32(const void* p) {
    return (uint32_t)__cvta_generic_to_shared(p);
}
__device__ __forceinline__ uint32_t sw128(uint32_t off) {
    return off ^ ((off >> 3) & 0x70u);
}

// ---------------------------------------------------------------------------
// Prep: transpose + fp16(emb*16)
// ---------------------------------------------------------------------------
__global__ void prep_transpose(const float* __restrict__ emb) {
    __shared__ float tile[32][33];
    const int v0 = blockIdx.x * 32, d0 = blockIdx.y * 32, t = threadIdx.x;
#pragma unroll
    for (int it = 0; it < 4; ++it) {
        int idx = t + it * 256, i = idx >> 5, j = idx & 31;
        tile[i][j] = emb[(size_t)(v0 + i) * DIM_D + d0 + j];
    }
    __syncthreads();
#pragma unroll
    for (int it = 0; it < 2; ++it) {
        int idx = t + it * 256, dl = idx >> 4, vp = idx & 15;
        __half2 h = __floats2half2_rn(tile[vp * 2][dl] * 16.0f,
                                      tile[vp * 2 + 1][dl] * 16.0f);
        *reinterpret_cast<__half2*>(
            &g_embT[(size_t)(d0 + dl) * DIM_V + v0 + vp * 2]) = h;
    }
}

// ---------------------------------------------------------------------------
// Producers (512 threads)
// ---------------------------------------------------------------------------
__device__ __forceinline__ void load_a(int4* va, const int* __restrict__ x,
                                       int m0, int stage, int t) {
    const int4* xr = reinterpret_cast<const int4*>(x);
    // 64 rows x 64 ints per stage; thread -> row = t>>3, 8 ints (2 int4)
    int row = t >> 3, q = t & 7;
    size_t o = (size_t)(m0 + row) * (DIM_V / 4) + (size_t)stage * 16 + q * 2;
    va[0] = xr[o];
    va[1] = xr[o + 1];
}

__device__ __forceinline__ void store_a(const int4* va, uint32_t abase,
                                        int t, int* flags) {
    int row = t >> 3, q = t & 7;
    const int* v = reinterpret_cast<const int*>(va);
    int any = 0;
    uint32_t pk[4];
#pragma unroll
    for (int j = 0; j < 4; ++j) {
        int v0 = v[2 * j], v1 = v[2 * j + 1];
        any |= v0 | v1;
        __half2 h = __floats2half2_rn((float)v0, (float)v1);
        pk[j] = *reinterpret_cast<uint32_t*>(&h);
    }
    if (any) flags[row] = 1;                 // benign same-value race
    uint32_t dst = abase + sw128((uint32_t)row * 128u + (uint32_t)q * 16u);
    asm volatile("st.shared.v4.b32 [%0], {%1,%2,%3,%4};"
                 :: "r"(dst), "r"(pk[0]), "r"(pk[1]), "r"(pk[2]), "r"(pk[3]));
}

__device__ __forceinline__ void issue_b(uint32_t bbase, int stage, int t) {
    const char* bsrc = reinterpret_cast<const char*>(g_embT);
#pragma unroll
    for (int i = 0; i < 4; ++i) {
        int idx = t + i * 512;
        int row = idx >> 3, seg = idx & 7;   // 256 rows x 8 x 16B
        uint32_t dst = bbase + sw128((uint32_t)row * 128u + (uint32_t)seg * 16u);
        const void* src = bsrc + (size_t)row * (DIM_V * 2)
                               + (size_t)stage * 128 + seg * 16;
        asm volatile("cp.async.cg.shared.global [%0], [%1], 16;"
                     :: "r"(dst), "l"(src));
    }
}

// ---------------------------------------------------------------------------
// GEMM: 128 CTAs x 512 thr; CTA 64x256; 16 warps 2Mx8N; warp 32x32; K=8192.
// ---------------------------------------------------------------------------
__global__ __launch_bounds__(512, 1)
void multihot_gemm(const int* __restrict__ x, const float* __restrict__ pos,
                   float* __restrict__ out) {
    extern __shared__ char dynsm[];
    __shared__ int flags[TM];

    const int t = threadIdx.x;
    const int wid = t >> 5, lane = t & 31;
    const int wm = wid & 1, wn = wid >> 1;   // wm 0..1 (M), wn 0..7 (N)
    const int m0 = blockIdx.x * TM;

    const uint32_t base = (smem_u32(dynsm) + 1023u) & ~1023u;

    for (int i = t; i < TM; i += 512) flags[i] = 0;
    __syncthreads();

    float acc[2][4][4];
#pragma unroll
    for (int a = 0; a < 2; ++a)
#pragma unroll
        for (int b = 0; b < 4; ++b)
#pragma unroll
            for (int c = 0; c < 4; ++c) acc[a][b][c] = 0.0f;

    // prologue: stages 0..2
    int4 va[2];
    load_a(va, x, m0, 0, t);
#pragma unroll
    for (int s = 0; s < RING - 1; ++s) {
        uint32_t sb = base + (uint32_t)s * ST_BYTES;
        store_a(va, sb, t, flags);
        issue_b(sb + A_BYTES, s, t);
        asm volatile("cp.async.commit_group;" ::: "memory");
        load_a(va, x, m0, s + 1, t);
    }

    // per-lane ldmatrix addresses (128B rows; swizzle xor = (row&7)<<4)
    const uint32_t a_khalf = (uint32_t)(lane >> 4) << 4;
    const uint32_t a_rxor  = (uint32_t)(lane & 7) << 4;
    uint32_t a_row[2];
#pragma unroll
    for (int mt = 0; mt < 2; ++mt)
        a_row[mt] = (uint32_t)(wm * 32 + mt * 16 + (lane & 15)) * 128u;

    const uint32_t b_khalf = (uint32_t)((lane >> 3) & 1) << 4;
    uint32_t b_row[2], b_rxor[2];
#pragma unroll
    for (int ntp = 0; ntp < 2; ++ntp) {
        int nrow = wn * 32 + ntp * 16 + (lane & 7) + ((lane >> 4) << 3);
        b_row[ntp]  = (uint32_t)nrow * 128u;
        b_rxor[ntp] = (uint32_t)(nrow & 7) << 4;
    }

    // mainloop
#pragma unroll 1
    for (int k = 0; k < NSTAGE; ++k) {
        asm volatile("cp.async.wait_group %0;" :: "n"(RING - 2) : "memory");
        __syncthreads();

        if (k + RING - 1 < NSTAGE) {
            uint32_t sb = base + (uint32_t)((k + RING - 1) & (RING - 1)) * ST_BYTES;
            store_a(va, sb, t, flags);
            issue_b(sb + A_BYTES, k + RING - 1, t);
        }
        if (k + RING < NSTAGE) load_a(va, x, m0, k + RING, t);
        asm volatile("cp.async.commit_group;" ::: "memory");

        const uint32_t soff = (uint32_t)(k & (RING - 1)) * ST_BYTES;
        const uint32_t ab = base + soff;
        const uint32_t bb = base + soff + A_BYTES;
#pragma unroll
        for (int ks = 0; ks < 4; ++ks) {
            const uint32_t kb = (uint32_t)ks * 32u;
            uint32_t af[2][4];
#pragma unroll
            for (int mt = 0; mt < 2; ++mt) {
                uint32_t addr = ab + a_row[mt] + ((kb + a_khalf) ^ a_rxor);
                asm volatile("ldmatrix.sync.aligned.m8n8.x4.shared.b16 "
                             "{%0,%1,%2,%3}, [%4];"
                             : "=r"(af[mt][0]), "=r"(af[mt][1]),
                               "=r"(af[mt][2]), "=r"(af[mt][3])
                             : "r"(addr));
            }
            uint32_t bf[2][4];
#pragma unroll
            for (int ntp = 0; ntp < 2; ++ntp) {
                uint32_t addr = bb + b_row[ntp] + ((kb + b_khalf) ^ b_rxor[ntp]);
                asm volatile("ldmatrix.sync.aligned.m8n8.x4.shared.b16 "
                             "{%0,%1,%2,%3}, [%4];"
                             : "=r"(bf[ntp][0]), "=r"(bf[ntp][1]),
                               "=r"(bf[ntp][2]), "=r"(bf[ntp][3])
                             : "r"(addr));
            }
#pragma unroll
            for (int mt = 0; mt < 2; ++mt) {
#pragma unroll
                for (int nt = 0; nt < 4; ++nt) {
                    float* c = acc[mt][nt];
                    const uint32_t* bp = &bf[nt >> 1][(nt & 1) * 2];
                    asm volatile(
                        "mma.sync.aligned.m16n8k16.row.col.f32.f16.f16.f32 "
                        "{%0,%1,%2,%3}, {%4,%5,%6,%7}, {%8,%9}, {%0,%1,%2,%3};"
                        : "+f"(c[0]), "+f"(c[1]), "+f"(c[2]), "+f"(c[3])
                        : "r"(af[mt][0]), "r"(af[mt][1]),
                          "r"(af[mt][2]), "r"(af[mt][3]),
                          "r"(bp[0]), "r"(bp[1]));
                }
            }
        }
    }

    __syncthreads();   // flags fully written

    // epilogue: out = acc + pos*any_tok  (x16 folded into table)
#pragma unroll
    for (int mt = 0; mt < 2; ++mt) {
#pragma unroll
        for (int half = 0; half < 2; ++half) {
            const int rl = wm * 32 + mt * 16 + (lane >> 2) + half * 8;
            const int grow = m0 + rl;
            const float tokf = flags[rl] ? 1.0f : 0.0f;
            const float* prow = pos + (size_t)(grow & (DIM_S - 1)) * DIM_D;
            float* orow = out + (size_t)grow * DIM_D;
#pragma unroll
            for (int nt = 0; nt < 4; ++nt) {
                const int col = wn * 32 + nt * 8 + (lane & 3) * 2;
                float2 pv = *reinterpret_cast<const float2*>(prow + col);
                float2 ov;
                ov.x = acc[mt][nt][half * 2 + 0] + pv.x * tokf;
                ov.y = acc[mt][nt][half * 2 + 1] + pv.y * tokf;
                *reinterpret_cast<float2*>(orow + col) = ov;
            }
        }
    }
}

// ---------------------------------------------------------------------------
extern "C" void kernel_launch(void* const* d_in, const int* in_sizes, int n_in,
                              void* d_out, int out_size) {
    (void)in_sizes; (void)n_in; (void)out_size;
    const int*   x   = (const int*)d_in[0];     // [8,1024,8192] int32 (0/1)
    const float* emb = (const float*)d_in[1];   // [8192,256] f32
    const float* pos = (const float*)d_in[2];   // [1,1024,256] f32
    float* out = (float*)d_out;                 // [8,1024,256] f32

    cudaFuncSetAttribute(multihot_gemm,
                         cudaFuncAttributeMaxDynamicSharedMemorySize, SMEM_DYN);

    prep_transpose<<<dim3(DIM_V / 32, DIM_D / 32), 256>>>(emb);
    multihot_gemm<<<(8 * DIM_S) / TM, 512, SMEM_DYN>>>(x, pos, out);
}

// round 9
// speedup vs baseline: 4.4427x; 1.0667x over previous
#include <cuda_runtime.h>
#include <cuda_fp16.h>
#include <cstdint>
#include <cstddef>

// out[b,s,d] = 16*sum_v x[b,s,v]*emb[v,d] + pos[s,d]*any(x[b,s,:])
// GEMM M=8192, N=256, K=8192. fp16 table = fp16(emb*16), x exact in fp16,
// fp32 accumulate (rel-RMS ~2.8e-4). Baseline PTX (no tcgen05 on compute_103).
// R9: intra-stage fragment double-buffering to kill LDSM->MMA serialization.

static constexpr int DIM_S = 1024;
static constexpr int DIM_V = 8192;
static constexpr int DIM_D = 256;

static constexpr int TM     = 64;           // CTA M tile
static constexpr int TKB    = 64;           // K per stage
static constexpr int NSTAGE = DIM_V / TKB;  // 128
static constexpr int RING   = 4;

static constexpr uint32_t A_BYTES  = TM * TKB * 2;        // 8 KB
static constexpr uint32_t B_BYTES  = DIM_D * TKB * 2;     // 32 KB
static constexpr uint32_t ST_BYTES = A_BYTES + B_BYTES;   // 40 KB
static constexpr uint32_t SMEM_DYN = RING * ST_BYTES + 1024;

// Transposed fp16 table: [d][v], value = fp16(emb[v][d] * 16). 4 MB.
__device__ __align__(128) unsigned short g_embT[(size_t)DIM_D * DIM_V];

__device__ __forceinline__ uint32_t smem_u32(const void* p) {
    return (uint32_t)__cvta_generic_to_shared(p);
}
__device__ __forceinline__ uint32_t sw128(uint32_t off) {
    return off ^ ((off >> 3) & 0x70u);
}

// ---------------------------------------------------------------------------
// Prep: transpose + fp16(emb*16)
// ---------------------------------------------------------------------------
__global__ void prep_transpose(const float* __restrict__ emb) {
    __shared__ float tile[32][33];
    const int v0 = blockIdx.x * 32, d0 = blockIdx.y * 32, t = threadIdx.x;
#pragma unroll
    for (int it = 0; it < 4; ++it) {
        int idx = t + it * 256, i = idx >> 5, j = idx & 31;
        tile[i][j] = emb[(size_t)(v0 + i) * DIM_D + d0 + j];
    }
    __syncthreads();
#pragma unroll
    for (int it = 0; it < 2; ++it) {
        int idx = t + it * 256, dl = idx >> 4, vp = idx & 15;
        __half2 h = __floats2half2_rn(tile[vp * 2][dl] * 16.0f,
                                      tile[vp * 2 + 1][dl] * 16.0f);
        *reinterpret_cast<__half2*>(
            &g_embT[(size_t)(d0 + dl) * DIM_V + v0 + vp * 2]) = h;
    }
}

// ---------------------------------------------------------------------------
// Producers (512 threads)
// ---------------------------------------------------------------------------
__device__ __forceinline__ void load_a(int4* va, const int* __restrict__ x,
                                       int m0, int stage, int t) {
    const int4* xr = reinterpret_cast<const int4*>(x);
    int row = t >> 3, q = t & 7;
    size_t o = (size_t)(m0 + row) * (DIM_V / 4) + (size_t)stage * 16 + q * 2;
    va[0] = xr[o];
    va[1] = xr[o + 1];
}

__device__ __forceinline__ void store_a(const int4* va, uint32_t abase,
                                        int t, int* flags) {
    int row = t >> 3, q = t & 7;
    const int* v = reinterpret_cast<const int*>(va);
    int any = 0;
    uint32_t pk[4];
#pragma unroll
    for (int j = 0; j < 4; ++j) {
        int v0 = v[2 * j], v1 = v[2 * j + 1];
        any |= v0 | v1;
        __half2 h = __floats2half2_rn((float)v0, (float)v1);
        pk[j] = *reinterpret_cast<uint32_t*>(&h);
    }
    if (any) flags[row] = 1;                 // benign same-value race
    uint32_t dst = abase + sw128((uint32_t)row * 128u + (uint32_t)q * 16u);
    asm volatile("st.shared.v4.b32 [%0], {%1,%2,%3,%4};"
                 :: "r"(dst), "r"(pk[0]), "r"(pk[1]), "r"(pk[2]), "r"(pk[3]));
}

__device__ __forceinline__ void issue_b(uint32_t bbase, int stage, int t) {
    const char* bsrc = reinterpret_cast<const char*>(g_embT);
#pragma unroll
    for (int i = 0; i < 4; ++i) {
        int idx = t + i * 512;
        int row = idx >> 3, seg = idx & 7;   // 256 rows x 8 x 16B
        uint32_t dst = bbase + sw128((uint32_t)row * 128u + (uint32_t)seg * 16u);
        const void* src = bsrc + (size_t)row * (DIM_V * 2)
                               + (size_t)stage * 128 + seg * 16;
        asm volatile("cp.async.cg.shared.global [%0], [%1], 16;"
                     :: "r"(dst), "l"(src));
    }
}

// ---------------------------------------------------------------------------
// GEMM: 128 CTAs x 512 thr; CTA 64x256; 16 warps 2Mx8N; warp 32x32.
// ---------------------------------------------------------------------------
__global__ __launch_bounds__(512, 1)
void multihot_gemm(const int* __restrict__ x, const float* __restrict__ pos,
                   float* __restrict__ out) {
    extern __shared__ char dynsm[];
    __shared__ int flags[TM];

    const int t = threadIdx.x;
    const int wid = t >> 5, lane = t & 31;
    const int wm = wid & 1, wn = wid >> 1;   // wm 0..1 (M), wn 0..7 (N)
    const int m0 = blockIdx.x * TM;

    const uint32_t base = (smem_u32(dynsm) + 1023u) & ~1023u;

    for (int i = t; i < TM; i += 512) flags[i] = 0;
    __syncthreads();

    float acc[2][4][4];
#pragma unroll
    for (int a = 0; a < 2; ++a)
#pragma unroll
        for (int b = 0; b < 4; ++b)
#pragma unroll
            for (int c = 0; c < 4; ++c) acc[a][b][c] = 0.0f;

    // prologue: stages 0..2
    int4 va[2];
    load_a(va, x, m0, 0, t);
#pragma unroll
    for (int s = 0; s < RING - 1; ++s) {
        uint32_t sb = base + (uint32_t)s * ST_BYTES;
        store_a(va, sb, t, flags);
        issue_b(sb + A_BYTES, s, t);
        asm volatile("cp.async.commit_group;" ::: "memory");
        load_a(va, x, m0, s + 1, t);
    }

    // per-lane ldmatrix addresses (128B rows; swizzle xor = (row&7)<<4)
    const uint32_t a_khalf = (uint32_t)(lane >> 4) << 4;
    const uint32_t a_rxor  = (uint32_t)(lane & 7) << 4;
    uint32_t a_row[2];
#pragma unroll
    for (int mt = 0; mt < 2; ++mt)
        a_row[mt] = (uint32_t)(wm * 32 + mt * 16 + (lane & 15)) * 128u;

    const uint32_t b_khalf = (uint32_t)((lane >> 3) & 1) << 4;
    uint32_t b_row[2], b_rxor[2];
#pragma unroll
    for (int ntp = 0; ntp < 2; ++ntp) {
        int nrow = wn * 32 + ntp * 16 + (lane & 7) + ((lane >> 4) << 3);
        b_row[ntp]  = (uint32_t)nrow * 128u;
        b_rxor[ntp] = (uint32_t)(nrow & 7) << 4;
    }

    // Fragment load (one k-slice) into given buffers.
#define LOAD_FRAGS(AF, BF, AB, BB, KS)                                         \
    do {                                                                       \
        const uint32_t kb = (uint32_t)(KS) * 32u;                              \
        _Pragma("unroll")                                                      \
        for (int mt = 0; mt < 2; ++mt) {                                       \
            uint32_t addr = (AB) + a_row[mt] + ((kb + a_khalf) ^ a_rxor);      \
            asm volatile("ldmatrix.sync.aligned.m8n8.x4.shared.b16 "           \
                         "{%0,%1,%2,%3}, [%4];"                                \
                         : "=r"((AF)[mt][0]), "=r"((AF)[mt][1]),               \
                           "=r"((AF)[mt][2]), "=r"((AF)[mt][3])                \
                         : "r"(addr));                                         \
        }                                                                      \
        _Pragma("unroll")                                                      \
        for (int ntp = 0; ntp < 2; ++ntp) {                                    \
            uint32_t addr = (BB) + b_row[ntp] + ((kb + b_khalf) ^ b_rxor[ntp]);\
            asm volatile("ldmatrix.sync.aligned.m8n8.x4.shared.b16 "           \
                         "{%0,%1,%2,%3}, [%4];"                                \
                         : "=r"((BF)[ntp][0]), "=r"((BF)[ntp][1]),             \
                           "=r"((BF)[ntp][2]), "=r"((BF)[ntp][3])              \
                         : "r"(addr));                                         \
        }                                                                      \
    } while (0)

    // MMA set on buffers (non-volatile: ordered by register dependencies).
#define MMA_SET(AF, BF)                                                        \
    do {                                                                       \
        _Pragma("unroll")                                                      \
        for (int mt = 0; mt < 2; ++mt) {                                       \
            _Pragma("unroll")                                                  \
            for (int nt = 0; nt < 4; ++nt) {                                   \
                float* c = acc[mt][nt];                                        \
                const uint32_t* bp = &(BF)[nt >> 1][(nt & 1) * 2];             \
                asm("mma.sync.aligned.m16n8k16.row.col.f32.f16.f16.f32 "       \
                    "{%0,%1,%2,%3}, {%4,%5,%6,%7}, {%8,%9}, {%0,%1,%2,%3};"    \
                    : "+f"(c[0]), "+f"(c[1]), "+f"(c[2]), "+f"(c[3])           \
                    : "r"((AF)[mt][0]), "r"((AF)[mt][1]),                      \
                      "r"((AF)[mt][2]), "r"((AF)[mt][3]),                      \
                      "r"(bp[0]), "r"(bp[1]));                                 \
            }                                                                  \
        }                                                                      \
    } while (0)

    uint32_t af0[2][4], bf0[2][4], af1[2][4], bf1[2][4];

    // mainloop
#pragma unroll 1
    for (int k = 0; k < NSTAGE; ++k) {
        asm volatile("cp.async.wait_group %0;" :: "n"(RING - 2) : "memory");
        __syncthreads();

        const uint32_t soff = (uint32_t)(k & (RING - 1)) * ST_BYTES;
        const uint32_t ab = base + soff;
        const uint32_t bb = base + soff + A_BYTES;

        // start ks0 fragment loads early: latency overlaps producer work
        LOAD_FRAGS(af0, bf0, ab, bb, 0);

        if (k + RING - 1 < NSTAGE) {
            uint32_t sb = base + (uint32_t)((k + RING - 1) & (RING - 1)) * ST_BYTES;
            store_a(va, sb, t, flags);
            issue_b(sb + A_BYTES, k + RING - 1, t);
        }
        if (k + RING < NSTAGE) load_a(va, x, m0, k + RING, t);
        asm volatile("cp.async.commit_group;" ::: "memory");

        // ks-pipelined: load ks+1 while issuing MMAs of ks
        LOAD_FRAGS(af1, bf1, ab, bb, 1);
        MMA_SET(af0, bf0);
        LOAD_FRAGS(af0, bf0, ab, bb, 2);
        MMA_SET(af1, bf1);
        LOAD_FRAGS(af1, bf1, ab, bb, 3);
        MMA_SET(af0, bf0);
        MMA_SET(af1, bf1);
    }

    __syncthreads();   // flags fully written

    // epilogue: out = acc + pos*any_tok  (x16 folded into table)
#pragma unroll
    for (int mt = 0; mt < 2; ++mt) {
#pragma unroll
        for (int half = 0; half < 2; ++half) {
            const int rl = wm * 32 + mt * 16 + (lane >> 2) + half * 8;
            const int grow = m0 + rl;
            const float tokf = flags[rl] ? 1.0f : 0.0f;
            const float* prow = pos + (size_t)(grow & (DIM_S - 1)) * DIM_D;
            float* orow = out + (size_t)grow * DIM_D;
#pragma unroll
            for (int nt = 0; nt < 4; ++nt) {
                const int col = wn * 32 + nt * 8 + (lane & 3) * 2;
                float2 pv = *reinterpret_cast<const float2*>(prow + col);
                float2 ov;
                ov.x = acc[mt][nt][half * 2 + 0] + pv.x * tokf;
                ov.y = acc[mt][nt][half * 2 + 1] + pv.y * tokf;
                *reinterpret_cast<float2*>(orow + col) = ov;
            }
        }
    }
}

// ---------------------------------------------------------------------------
extern "C" void kernel_launch(void* const* d_in, const int* in_sizes, int n_in,
                              void* d_out, int out_size) {
    (void)in_sizes; (void)n_in; (void)out_size;
    const int*   x   = (const int*)d_in[0];     // [8,1024,8192] int32 (0/1)
    const float* emb = (const float*)d_in[1];   // [8192,256] f32
    const float* pos = (const float*)d_in[2];   // [1,1024,256] f32
    float* out = (float*)d_out;                 // [8,1024,256] f32

    cudaFuncSetAttribute(multihot_gemm,
                         cudaFuncAttributeMaxDynamicSharedMemorySize, SMEM_DYN);

    prep_transpose<<<dim3(DIM_V / 32, DIM_D / 32), 256>>>(emb);
    multihot_gemm<<<(8 * DIM_S) / TM, 512, SMEM_DYN>>>(x, pos, out);
}